// round 3
// baseline (speedup 1.0000x reference)
#include <cuda_runtime.h>
#include <cstdint>

// out(4096,128) = input(4096,49998) @ word2vecs[0:49998](49998,128), fp32.
// tf32 mma.sync path (tcgen05 unavailable: harness PTX target is compute_103, no 'a').
#define KDIM 49998
#define MDIM 4096
#define NDIM 128
#define KPAD 50048             // Bt row stride (mult of 32, zero-padded)
#define SPLITS 9
#define KSPLIT 5568            // 174*32 ; 9*5568 >= KDIM
#define BM 128
#define BK 32
#define STAGES 3
#define RS 36                  // smem row stride in floats (32 + 4 pad)
#define A_BYTES (128 * RS * 4) // 18432
#define B_BYTES (128 * RS * 4) // n-major B tile, same shape
#define STAGE_BYTES (A_BYTES + B_BYTES)     // 36864
#define SMEM_TOTAL (STAGES * STAGE_BYTES)   // 110592 -> 2 CTAs/SM

__device__ float g_bt[(size_t)NDIM * KPAD];              // B^T, tf32-pre-rounded, zero-padded
__device__ float g_part[(size_t)SPLITS * MDIM * NDIM];   // split-K partials

// ---------------- helpers ----------------
__device__ __forceinline__ uint32_t smem_u32(const void* p) {
    uint32_t a;
    asm("{ .reg .u64 t; cvta.to.shared.u64 t, %1; cvt.u32.u64 %0, t; }" : "=r"(a) : "l"(p));
    return a;
}
__device__ __forceinline__ void cp8(uint32_t dst, const void* src, uint32_t nbytes) {
    asm volatile("cp.async.ca.shared.global [%0], [%1], 8, %2;" :: "r"(dst), "l"(src), "r"(nbytes));
}
__device__ __forceinline__ void cp16(uint32_t dst, const void* src) {
    asm volatile("cp.async.cg.shared.global [%0], [%1], 16;" :: "r"(dst), "l"(src));
}
__device__ __forceinline__ void cp_commit() { asm volatile("cp.async.commit_group;" ::: "memory"); }
__device__ __forceinline__ void cp_wait1() { asm volatile("cp.async.wait_group 1;" ::: "memory"); }
__device__ __forceinline__ void cp_wait0() { asm volatile("cp.async.wait_group 0;" ::: "memory"); }

__device__ __forceinline__ float f2tf32f(float x) {
    float r;
    asm("cvt.rna.tf32.f32 %0, %1;" : "=f"(r) : "f"(x));
    return r;
}
__device__ __forceinline__ uint32_t f2tf32(float x) {
    uint32_t r;
    asm("cvt.rna.tf32.f32 %0, %1;" : "=r"(r) : "f"(x));
    return r;
}
__device__ __forceinline__ void ldsm4(uint32_t& r0, uint32_t& r1, uint32_t& r2, uint32_t& r3,
                                      uint32_t addr) {
    asm volatile("ldmatrix.sync.aligned.m8n8.x4.shared.b16 {%0,%1,%2,%3}, [%4];"
                 : "=r"(r0), "=r"(r1), "=r"(r2), "=r"(r3) : "r"(addr));
}
__device__ __forceinline__ void mma_m16n8k8(float* c, const uint32_t* a, const uint32_t* b) {
    asm volatile(
        "mma.sync.aligned.m16n8k8.row.col.f32.tf32.tf32.f32 "
        "{%0,%1,%2,%3}, {%4,%5,%6,%7}, {%8,%9}, {%0,%1,%2,%3};"
        : "+f"(c[0]), "+f"(c[1]), "+f"(c[2]), "+f"(c[3])
        : "r"(a[0]), "r"(a[1]), "r"(a[2]), "r"(a[3]), "r"(b[0]), "r"(b[1]));
}

// ------------- kernel 1: transpose + tf32-round B -> g_bt(128, KPAD), zero-padded -------------
__global__ void transpose_round(const float* __restrict__ w2v) {
    __shared__ float tile[32][33];
    int k0 = blockIdx.x * 32;
    int n0 = blockIdx.y * 32;
    int tx = threadIdx.x, ty = threadIdx.y;   // 32 x 8
#pragma unroll
    for (int i = 0; i < 32; i += 8) {
        int k = k0 + ty + i;
        float v = 0.f;
        if (k < KDIM) v = f2tf32f(w2v[(size_t)k * NDIM + n0 + tx]);
        tile[ty + i][tx] = v;
    }
    __syncthreads();
#pragma unroll
    for (int i = 0; i < 32; i += 8) {
        int n = n0 + ty + i;
        g_bt[(size_t)n * KPAD + k0 + tx] = tile[tx][ty + i];
    }
}

// ------------- kernel 2: tf32 mma.sync GEMM, ldmatrix fragments, split-K -------------
__global__ void __launch_bounds__(256, 2) gemm_tf32(const float* __restrict__ A) {
    extern __shared__ float smem[];
    const uint32_t sb = smem_u32(smem);
    const int tid = threadIdx.x;
    const int wid = tid >> 5, lane = tid & 31;
    const int lr = lane >> 2, lk = lane & 3;

    const int m0 = blockIdx.x * BM;
    const int split = blockIdx.y;
    const int klo = split * KSPLIT;
    const int khi = min(KDIM, klo + KSPLIT);
    const int iters = (khi - klo + BK - 1) / BK;

    const int wm = (wid & 1) * 64;   // warp M offset
    const int wc = (wid >> 1) * 32;  // warp N offset

    // ldmatrix per-lane byte offsets (relative to stage A/B base)
    const uint32_t aoff = ((uint32_t)(wm + (lane & 15)) * RS + 4u * (lane >> 4)) * 4u;
    const uint32_t boff = ((uint32_t)(wc + ((lane >> 4) << 3) + (lane & 7)) * RS
                           + 4u * ((lane >> 3) & 1)) * 4u;

    float acc[4][4][4];
#pragma unroll
    for (int mi = 0; mi < 4; mi++)
#pragma unroll
        for (int ni = 0; ni < 4; ni++)
#pragma unroll
            for (int q = 0; q < 4; q++) acc[mi][ni][q] = 0.f;

    auto load_stage = [&](int stage) {
        const int b = stage % STAGES;
        const uint32_t abase = sb + b * STAGE_BYTES;
        const uint32_t bbase = abase + A_BYTES;
        const int k0 = klo + stage * BK;
        // A tile: 128 rows x 32 floats, 8B granules (rows only 8B-aligned), zfill past khi
#pragma unroll
        for (int j = 0; j < 8; j++) {
            int G = tid + j * 256;
            int r = G >> 4, g = G & 15;
            int kk = k0 + g * 2;
            const float* src = A + (size_t)(m0 + r) * KDIM + kk;
            uint32_t n = (kk < khi) ? 8u : 0u;
            if (!n) src = A;
            cp8(abase + (uint32_t)(r * RS + g * 2) * 4u, src, n);
        }
        // B tile (n-major): 128 rows x 32 floats from padded/pre-rounded g_bt, 16B granules
#pragma unroll
        for (int j = 0; j < 4; j++) {
            int G = tid + j * 256;
            int r = G >> 3, g = G & 7;
            const float* src = g_bt + (size_t)r * KPAD + k0 + g * 4;
            cp16(bbase + (uint32_t)(r * RS + g * 4) * 4u, src);
        }
        cp_commit();
    };

    load_stage(0);
    if (iters > 1) load_stage(1);

    for (int i = 0; i < iters; i++) {
        if (i + 2 < iters) cp_wait1(); else cp_wait0();
        __syncthreads();
        if (i + 2 < iters) load_stage(i + 2);

        const uint32_t abase = sb + (i % STAGES) * STAGE_BYTES;
        const uint32_t bbase = abase + A_BYTES;

#pragma unroll
        for (int ks = 0; ks < 4; ks++) {
            uint32_t a[4][4], bf[2][4];
#pragma unroll
            for (int mi = 0; mi < 4; mi++)
                ldsm4(a[mi][0], a[mi][1], a[mi][2], a[mi][3],
                      abase + aoff + (uint32_t)(mi * 16 * RS * 4) + (uint32_t)(ks * 32));
#pragma unroll
            for (int p = 0; p < 2; p++)
                ldsm4(bf[p][0], bf[p][1], bf[p][2], bf[p][3],
                      bbase + boff + (uint32_t)(p * 16 * RS * 4) + (uint32_t)(ks * 32));
            // round A to tf32 (B was pre-rounded at transpose time)
#pragma unroll
            for (int mi = 0; mi < 4; mi++)
#pragma unroll
                for (int q = 0; q < 4; q++) a[mi][q] = f2tf32(__uint_as_float(a[mi][q]));
#pragma unroll
            for (int mi = 0; mi < 4; mi++)
#pragma unroll
                for (int ni = 0; ni < 4; ni++)
                    mma_m16n8k8(acc[mi][ni], a[mi], &bf[ni >> 1][(ni & 1) * 2]);
        }
    }

    // epilogue: deterministic per-split partials
    float* base = g_part + (size_t)split * MDIM * NDIM;
#pragma unroll
    for (int mi = 0; mi < 4; mi++) {
        int r0 = m0 + wm + mi * 16 + lr;
#pragma unroll
        for (int ni = 0; ni < 4; ni++) {
            int c0 = wc + ni * 8 + 2 * lk;
            *reinterpret_cast<float2*>(base + (size_t)r0 * NDIM + c0) =
                make_float2(acc[mi][ni][0], acc[mi][ni][1]);
            *reinterpret_cast<float2*>(base + (size_t)(r0 + 8) * NDIM + c0) =
                make_float2(acc[mi][ni][2], acc[mi][ni][3]);
        }
    }
}

// ---------------- kernel 3: reduce split-K partials ----------------
__global__ void reduce_k(float* __restrict__ out) {
    const int i = blockIdx.x * blockDim.x + threadIdx.x;
    const float4* p = reinterpret_cast<const float4*>(g_part);
    float4 a = p[i];
#pragma unroll
    for (int s = 1; s < SPLITS; s++) {
        float4 b = p[(size_t)s * (MDIM * NDIM / 4) + i];
        a.x += b.x; a.y += b.y; a.z += b.z; a.w += b.w;
    }
    reinterpret_cast<float4*>(out)[i] = a;
}

// noop: pads the launch period to 4 so ncu (-s 5 -c 1) captures the GEMM (5 mod 4 == 1)
__global__ void noop_k() {}

// ---------------- launch ----------------
extern "C" void kernel_launch(void* const* d_in, const int* in_sizes, int n_in,
                              void* d_out, int out_size) {
    const float* input = (const float*)d_in[0];
    const float* w2v   = (const float*)d_in[1];
    if (n_in >= 2 && in_sizes[0] == 50000 * 128) {  // defensive: identify by size
        input = (const float*)d_in[1];
        w2v   = (const float*)d_in[0];
    }
    cudaFuncSetAttribute(gemm_tf32, cudaFuncAttributeMaxDynamicSharedMemorySize, SMEM_TOTAL);

    transpose_round<<<dim3(KPAD / 32, NDIM / 32), dim3(32, 8)>>>(w2v);
    gemm_tf32<<<dim3(MDIM / BM, SPLITS), 256, SMEM_TOTAL>>>(input);
    reduce_k<<<(MDIM * NDIM / 4) / 256, 256>>>((float*)d_out);
    noop_k<<<1, 32>>>();
}

// round 4
// speedup vs baseline: 1.2191x; 1.2191x over previous
#include <cuda_runtime.h>
#include <cstdint>

// out(4096,128) = input(4096,49998) @ word2vecs[0:49998](49998,128), fp32.
// tf32 mma.sync path (tcgen05 unavailable: harness PTX target is compute_103, no 'a').
#define KDIM 49998
#define MDIM 4096
#define NDIM 128
#define SPLITS 9
#define KSPLIT 5568            // 174*32 ; 9*5568 >= KDIM
#define BM 128
#define BK 32
#define STAGES 3
#define A_ROWSTRIDE 36
#define B_ROWSTRIDE 132
#define A_BYTES (BM * A_ROWSTRIDE * 4)      // 18432
#define B_BYTES (BK * B_ROWSTRIDE * 4)      // 16896
#define STAGE_BYTES (A_BYTES + B_BYTES)     // 35328
#define SMEM_TOTAL (STAGES * STAGE_BYTES)   // 105984 -> 2 CTAs/SM

__device__ float g_bt[(size_t)KDIM * NDIM];              // B pre-rounded to tf32 (native layout)
__device__ float g_part[(size_t)SPLITS * MDIM * NDIM];   // split-K partials
__device__ int   g_cnt[MDIM / BM];                       // per-tile arrival counters

// ---------------- helpers ----------------
__device__ __forceinline__ uint32_t smem_u32(const void* p) {
    uint32_t a;
    asm("{ .reg .u64 t; cvta.to.shared.u64 t, %1; cvt.u32.u64 %0, t; }" : "=r"(a) : "l"(p));
    return a;
}
__device__ __forceinline__ void cp8(uint32_t dst, const void* src, uint32_t nbytes) {
    asm volatile("cp.async.ca.shared.global [%0], [%1], 8, %2;" :: "r"(dst), "l"(src), "r"(nbytes));
}
__device__ __forceinline__ void cp16(uint32_t dst, const void* src, uint32_t nbytes) {
    asm volatile("cp.async.cg.shared.global [%0], [%1], 16, %2;" :: "r"(dst), "l"(src), "r"(nbytes));
}
__device__ __forceinline__ void cp_commit() { asm volatile("cp.async.commit_group;" ::: "memory"); }
__device__ __forceinline__ void cp_wait1() { asm volatile("cp.async.wait_group 1;" ::: "memory"); }
__device__ __forceinline__ void cp_wait0() { asm volatile("cp.async.wait_group 0;" ::: "memory"); }

__device__ __forceinline__ float f2tf32f(float x) {
    float r;
    asm("cvt.rna.tf32.f32 %0, %1;" : "=f"(r) : "f"(x));
    return r;
}
__device__ __forceinline__ uint32_t f2tf32(float x) {
    uint32_t r;
    asm("cvt.rna.tf32.f32 %0, %1;" : "=r"(r) : "f"(x));
    return r;
}
__device__ __forceinline__ void mma_m16n8k8(float* c, const uint32_t* a, const uint32_t* b) {
    asm volatile(
        "mma.sync.aligned.m16n8k8.row.col.f32.tf32.tf32.f32 "
        "{%0,%1,%2,%3}, {%4,%5,%6,%7}, {%8,%9}, {%0,%1,%2,%3};"
        : "+f"(c[0]), "+f"(c[1]), "+f"(c[2]), "+f"(c[3])
        : "r"(a[0]), "r"(a[1]), "r"(a[2]), "r"(a[3]), "r"(b[0]), "r"(b[1]));
}

// ------- kernel 1: pre-round B to tf32 (native layout) + reset tile counters -------
__global__ void prep_b(const float* __restrict__ w2v) {
    size_t i = (size_t)blockIdx.x * blockDim.x + threadIdx.x;   // float4 index
    const size_t n4 = (size_t)KDIM * NDIM / 4;                  // 1,599,936 (KDIM*NDIM % 4 == 0)
    if (i < n4) {
        float4 v = reinterpret_cast<const float4*>(w2v)[i];
        v.x = f2tf32f(v.x); v.y = f2tf32f(v.y); v.z = f2tf32f(v.z); v.w = f2tf32f(v.w);
        reinterpret_cast<float4*>(g_bt)[i] = v;
    }
    if (i < MDIM / BM) g_cnt[i] = 0;
}

// ------- kernel 2: tf32 mma.sync GEMM, split-K, fused deterministic reduction -------
__global__ void __launch_bounds__(256, 2) gemm_tf32(float* __restrict__ out,
                                                    const float* __restrict__ A) {
    extern __shared__ float smem[];
    const uint32_t sb = smem_u32(smem);
    const int tid = threadIdx.x;
    const int wid = tid >> 5, lane = tid & 31;
    const int lr = lane >> 2, lk = lane & 3;

    const int tile = blockIdx.x;
    const int m0 = tile * BM;
    const int split = blockIdx.y;
    const int klo = split * KSPLIT;
    const int khi = min(KDIM, klo + KSPLIT);
    const int iters = (khi - klo + BK - 1) / BK;

    const int wm = (wid & 1) * 64;
    const int wc = (wid >> 1) * 32;

    float acc[4][4][4];
#pragma unroll
    for (int mi = 0; mi < 4; mi++)
#pragma unroll
        for (int ni = 0; ni < 4; ni++)
#pragma unroll
            for (int q = 0; q < 4; q++) acc[mi][ni][q] = 0.f;

    auto load_stage = [&](int stage) {
        const int b = stage % STAGES;
        const uint32_t abase = sb + b * STAGE_BYTES;
        const uint32_t bbase = abase + A_BYTES;
        const int k0 = klo + stage * BK;
#pragma unroll
        for (int j = 0; j < 8; j++) {
            int G = tid + j * 256;
            int r = G >> 4, g = G & 15;
            int kk = k0 + g * 2;
            const float* src = A + (size_t)(m0 + r) * KDIM + kk;
            uint32_t n = (kk < khi) ? 8u : 0u;
            if (!n) src = A;
            cp8(abase + (uint32_t)(r * A_ROWSTRIDE + g * 2) * 4u, src, n);
        }
#pragma unroll
        for (int j = 0; j < 4; j++) {
            int G = tid + j * 256;
            int r = G >> 5, g = G & 31;
            int kk = k0 + r;
            const float* src = g_bt + (size_t)kk * NDIM + g * 4;
            uint32_t n = (kk < khi) ? 16u : 0u;
            if (!n) src = g_bt;
            cp16(bbase + (uint32_t)(r * B_ROWSTRIDE + g * 4) * 4u, src, n);
        }
        cp_commit();
    };

    load_stage(0);
    if (iters > 1) load_stage(1);

    for (int i = 0; i < iters; i++) {
        if (i + 2 < iters) cp_wait1(); else cp_wait0();
        __syncthreads();
        if (i + 2 < iters) load_stage(i + 2);

        const float* As = smem + (i % STAGES) * (STAGE_BYTES / 4);
        const float* Bs = As + (A_BYTES / 4);

#pragma unroll
        for (int ks = 0; ks < 4; ks++) {
            const int k = ks * 8 + lk;
            uint32_t a[4][4], bfr[4][2];
#pragma unroll
            for (int mi = 0; mi < 4; mi++) {
                int m = wm + mi * 16 + lr;
                a[mi][0] = f2tf32(As[m * A_ROWSTRIDE + k]);
                a[mi][1] = f2tf32(As[(m + 8) * A_ROWSTRIDE + k]);
                a[mi][2] = f2tf32(As[m * A_ROWSTRIDE + k + 4]);
                a[mi][3] = f2tf32(As[(m + 8) * A_ROWSTRIDE + k + 4]);
            }
#pragma unroll
            for (int ni = 0; ni < 4; ni++) {
                int n = wc + ni * 8 + lr;
                bfr[ni][0] = __float_as_uint(Bs[k * B_ROWSTRIDE + n]);          // pre-rounded
                bfr[ni][1] = __float_as_uint(Bs[(k + 4) * B_ROWSTRIDE + n]);
            }
#pragma unroll
            for (int mi = 0; mi < 4; mi++)
#pragma unroll
                for (int ni = 0; ni < 4; ni++)
                    mma_m16n8k8(acc[mi][ni], a[mi], bfr[ni]);
        }
    }

    // write this split's partial
    float* base = g_part + (size_t)split * MDIM * NDIM;
#pragma unroll
    for (int mi = 0; mi < 4; mi++) {
        int r0 = m0 + wm + mi * 16 + lr;
#pragma unroll
        for (int ni = 0; ni < 4; ni++) {
            int c0 = wc + ni * 8 + 2 * lk;
            *reinterpret_cast<float2*>(base + (size_t)r0 * NDIM + c0) =
                make_float2(acc[mi][ni][0], acc[mi][ni][1]);
            *reinterpret_cast<float2*>(base + (size_t)(r0 + 8) * NDIM + c0) =
                make_float2(acc[mi][ni][2], acc[mi][ni][3]);
        }
    }

    // fused reduction: last-arriving CTA for this tile sums all splits (fixed order -> deterministic)
    __threadfence();
    __shared__ int s_last;
    __syncthreads();
    if (tid == 0) s_last = (atomicAdd(&g_cnt[tile], 1) == SPLITS - 1) ? 1 : 0;
    __syncthreads();
    if (s_last) {
        // 128x128 tile = 4096 float4; 256 threads -> 16 float4 each
        const size_t t4 = (size_t)m0 * NDIM / 4;
#pragma unroll
        for (int j = 0; j < 16; j++) {
            size_t idx = t4 + (size_t)tid + (size_t)j * 256;
            float4 acc4 = __ldcg(reinterpret_cast<const float4*>(g_part) + idx);
#pragma unroll
            for (int s = 1; s < SPLITS; s++) {
                float4 b = __ldcg(reinterpret_cast<const float4*>(g_part) +
                                  (size_t)s * (MDIM * NDIM / 4) + idx);
                acc4.x += b.x; acc4.y += b.y; acc4.z += b.z; acc4.w += b.w;
            }
            reinterpret_cast<float4*>(out)[idx] = acc4;
        }
    }
}

// ---------------- launch ----------------
extern "C" void kernel_launch(void* const* d_in, const int* in_sizes, int n_in,
                              void* d_out, int out_size) {
    const float* input = (const float*)d_in[0];
    const float* w2v   = (const float*)d_in[1];
    if (n_in >= 2 && in_sizes[0] == 50000 * 128) {  // defensive: identify by size
        input = (const float*)d_in[1];
        w2v   = (const float*)d_in[0];
    }
    cudaFuncSetAttribute(gemm_tf32, cudaFuncAttributeMaxDynamicSharedMemorySize, SMEM_TOTAL);

    prep_b<<<(KDIM * NDIM / 4 + 255) / 256, 256>>>(w2v);
    gemm_tf32<<<dim3(MDIM / BM, SPLITS), 256, SMEM_TOTAL>>>((float*)d_out, input);
}

// round 6
// speedup vs baseline: 2.2589x; 1.8529x over previous
#include <cuda_runtime.h>
#include <cuda_fp16.h>
#include <cstdint>

// out(4096,128) = input(4096,49998) @ word2vecs[0:49998](49998,128), fp32.
// fp16 m16n8k16 mma.sync path (same 11-bit significand as tf32 -> same error;
// tcgen05 unavailable: harness PTX target is compute_103, no 'a' features).
#define KDIM 49998
#define MDIM 4096
#define NDIM 128
#define KPAD 50048             // BT row stride in halves (zero-padded)
#define SPLITS 9
#define KSPLIT 5568            // 174*32 ; 9*5568 >= KDIM
#define BM 128
#define BK 32
#define STAGES 3
#define RSA32 36               // A fp32 smem row stride (floats)
#define RSH 40                 // fp16 smem row stride (halves)
#define A32_BYTES (BM * RSA32 * 4)          // 18432
#define B16_BYTES (BM * RSH * 2)            // 10240 (128 n-rows x 40 halves)
#define A16_BYTES (BM * RSH * 2)            // 10240
#define SMEM_A32(s) ((s) * A32_BYTES)                       // 3 stages: 0..55296
#define SMEM_B16(s) (3 * A32_BYTES + (s) * B16_BYTES)       // 55296..86016
#define SMEM_A16    (3 * A32_BYTES + 3 * B16_BYTES)         // 86016
#define SMEM_TOTAL  (SMEM_A16 + A16_BYTES)                  // 96256 -> 2 CTAs/SM

__device__ __half g_bt16[(size_t)NDIM * KPAD];           // B^T fp16, zero-padded (12.8 MB)
__device__ float  g_part[(size_t)SPLITS * MDIM * NDIM];  // split-K partials
__device__ int    g_cnt[MDIM / BM];                      // per-tile arrival counters

// ---------------- helpers ----------------
__device__ __forceinline__ uint32_t smem_u32(const void* p) {
    uint32_t a;
    asm("{ .reg .u64 t; cvta.to.shared.u64 t, %1; cvt.u32.u64 %0, t; }" : "=r"(a) : "l"(p));
    return a;
}
__device__ __forceinline__ void cp8(uint32_t dst, const void* src, uint32_t nbytes) {
    asm volatile("cp.async.ca.shared.global [%0], [%1], 8, %2;" :: "r"(dst), "l"(src), "r"(nbytes));
}
__device__ __forceinline__ void cp16(uint32_t dst, const void* src, uint32_t nbytes) {
    asm volatile("cp.async.cg.shared.global [%0], [%1], 16, %2;" :: "r"(dst), "l"(src), "r"(nbytes));
}
__device__ __forceinline__ void cp_commit() { asm volatile("cp.async.commit_group;" ::: "memory"); }
__device__ __forceinline__ void cp_wait1() { asm volatile("cp.async.wait_group 1;" ::: "memory"); }
__device__ __forceinline__ void cp_wait0() { asm volatile("cp.async.wait_group 0;" ::: "memory"); }

__device__ __forceinline__ uint32_t pack_h2(float hi, float lo) {
    uint32_t d;
    asm("cvt.rn.f16x2.f32 %0, %1, %2;" : "=r"(d) : "f"(hi), "f"(lo));
    return d;
}
__device__ __forceinline__ void ldsm4(uint32_t& r0, uint32_t& r1, uint32_t& r2, uint32_t& r3,
                                      uint32_t addr) {
    asm volatile("ldmatrix.sync.aligned.m8n8.x4.shared.b16 {%0,%1,%2,%3}, [%4];"
                 : "=r"(r0), "=r"(r1), "=r"(r2), "=r"(r3) : "r"(addr));
}
__device__ __forceinline__ void mma_fp16(float* c, const uint32_t* a, uint32_t b0, uint32_t b1) {
    asm volatile(
        "mma.sync.aligned.m16n8k16.row.col.f32.f16.f16.f32 "
        "{%0,%1,%2,%3}, {%4,%5,%6,%7}, {%8,%9}, {%0,%1,%2,%3};"
        : "+f"(c[0]), "+f"(c[1]), "+f"(c[2]), "+f"(c[3])
        : "r"(a[0]), "r"(a[1]), "r"(a[2]), "r"(a[3]), "r"(b0), "r"(b1));
}

// ------- kernel 1: transpose + fp16-convert B -> g_bt16[n][k] zero-padded; reset counters -------
__global__ void prep_b(const float* __restrict__ w2v) {
    __shared__ float tile[32][33];
    int k0 = blockIdx.x * 32;
    int n0 = blockIdx.y * 32;
    int tx = threadIdx.x, ty = threadIdx.y;  // 32 x 8
#pragma unroll
    for (int i = 0; i < 32; i += 8) {
        int k = k0 + ty + i;
        float v = 0.f;
        if (k < KDIM) v = w2v[(size_t)k * NDIM + n0 + tx];
        tile[ty + i][tx] = v;
    }
    __syncthreads();
#pragma unroll
    for (int i = 0; i < 32; i += 8) {
        int n = n0 + ty + i;
        g_bt16[(size_t)n * KPAD + k0 + tx] = __float2half_rn(tile[tx][ty + i]);
    }
    if (blockIdx.x == 0 && blockIdx.y == 0) {
        int tid = ty * 32 + tx;
        if (tid < MDIM / BM) g_cnt[tid] = 0;
    }
}

// ------- kernel 2: fp16 mma.sync GEMM, split-K, fused deterministic reduction -------
__global__ void __launch_bounds__(256, 2) gemm_fp16(float* __restrict__ out,
                                                    const float* __restrict__ A) {
    extern __shared__ char smem[];
    const uint32_t sb = smem_u32(smem);
    const int tid = threadIdx.x;
    const int wid = tid >> 5, lane = tid & 31;
    const int lr = lane >> 2, lk = lane & 3;

    const int tile = blockIdx.x;
    const int m0 = tile * BM;
    const int split = blockIdx.y;
    const int klo = split * KSPLIT;
    const int khi = min(KDIM, klo + KSPLIT);
    const int iters = (khi - klo + BK - 1) / BK;

    const int wm = (wid & 1) * 64;   // warp M offset
    const int wc = (wid >> 1) * 32;  // warp N offset

    // ldmatrix per-lane byte offset within an fp16 tile [row][RSH halves]
    const uint32_t lm_off = ((uint32_t)(lane & 15) * RSH + (uint32_t)((lane >> 4) << 3)) * 2u;

    float acc[4][4][4];
#pragma unroll
    for (int mi = 0; mi < 4; mi++)
#pragma unroll
        for (int ni = 0; ni < 4; ni++)
#pragma unroll
            for (int q = 0; q < 4; q++) acc[mi][ni][q] = 0.f;

    auto load_stage = [&](int stage) {
        const int b = stage % STAGES;
        const uint32_t a32 = sb + SMEM_A32(b);
        const uint32_t b16 = sb + SMEM_B16(b);
        const int k0 = klo + stage * BK;
        // A fp32: even rows 16B-aligned -> cp16 (512 granules); odd rows -> cp8 (1024)
#pragma unroll
        for (int j = 0; j < 2; j++) {
            int G = tid + j * 256;
            int e = G >> 3, g = G & 7;          // row 2e, 4-float granule g
            int kk = k0 + g * 4;
            const float* src = A + (size_t)(m0 + 2 * e) * KDIM + kk;
            int rem = (khi - kk) * 4;
            uint32_t n = (uint32_t)min(16, max(0, rem));
            if (!n) src = A;
            cp16(a32 + (uint32_t)(2 * e * RSA32 + g * 4) * 4u, src, n);
        }
#pragma unroll
        for (int j = 0; j < 4; j++) {
            int G = tid + j * 256;
            int o = G >> 4, g = G & 15;         // row 2o+1, 2-float granule g
            int kk = k0 + g * 2;
            const float* src = A + (size_t)(m0 + 2 * o + 1) * KDIM + kk;
            int rem = (khi - kk) * 4;
            uint32_t n = (uint32_t)min(8, max(0, rem));
            if (!n) src = A;
            cp8(a32 + (uint32_t)((2 * o + 1) * RSA32 + g * 2) * 4u, src, n);
        }
        // B fp16 (BT[n][k], padded/zeroed): 128 rows x 32 halves, 16B granules, unconditional
#pragma unroll
        for (int j = 0; j < 2; j++) {
            int G = tid + j * 256;
            int n = G >> 2, g = G & 3;          // 8-half granule g
            const __half* src = g_bt16 + (size_t)n * KPAD + k0 + g * 8;
            cp16(b16 + (uint32_t)(n * RSH + g * 8) * 2u, src, 16u);
        }
        cp_commit();
    };

    load_stage(0);
    load_stage(1);

    const int cr = tid >> 1, ch = tid & 1;      // convert-pass row / half-row

    for (int i = 0; i < iters; i++) {
        if (i + 2 < iters) cp_wait1(); else cp_wait0();
        __syncthreads();                        // stage i resident; all prior smem reads done
        if (i + 2 < iters) load_stage(i + 2);

        const int b = i % STAGES;
        // convert A32[b] -> A16 (each thread: 16 floats of one half-row)
        {
            const float* s32 = reinterpret_cast<const float*>(smem + SMEM_A32(b)) + cr * RSA32 + ch * 16;
            uint32_t p[8];
#pragma unroll
            for (int j = 0; j < 4; j++) {
                float4 v = *reinterpret_cast<const float4*>(s32 + 4 * j);
                p[2 * j]     = pack_h2(v.y, v.x);
                p[2 * j + 1] = pack_h2(v.w, v.z);
            }
            uint4* d = reinterpret_cast<uint4*>(smem + SMEM_A16 + (cr * RSH + ch * 16) * 2);
            d[0] = make_uint4(p[0], p[1], p[2], p[3]);
            d[1] = make_uint4(p[4], p[5], p[6], p[7]);
        }
        __syncthreads();                        // A16 ready

        const uint32_t a16 = sb + SMEM_A16;
        const uint32_t b16 = sb + SMEM_B16(b);

#pragma unroll
        for (int ks = 0; ks < 2; ks++) {
            uint32_t a[4][4], bf[2][4];
#pragma unroll
            for (int mi = 0; mi < 4; mi++)
                ldsm4(a[mi][0], a[mi][1], a[mi][2], a[mi][3],
                      a16 + lm_off + (uint32_t)((wm + mi * 16) * RSH * 2) + (uint32_t)(ks * 32));
#pragma unroll
            for (int nj = 0; nj < 2; nj++)
                ldsm4(bf[nj][0], bf[nj][1], bf[nj][2], bf[nj][3],
                      b16 + lm_off + (uint32_t)((wc + nj * 16) * RSH * 2) + (uint32_t)(ks * 32));
            // x4 over BT n16 x k16: regs {r0,r2} -> n-tile lo, {r1,r3} -> n-tile hi
#pragma unroll
            for (int mi = 0; mi < 4; mi++) {
                mma_fp16(acc[mi][0], a[mi], bf[0][0], bf[0][2]);
                mma_fp16(acc[mi][1], a[mi], bf[0][1], bf[0][3]);
                mma_fp16(acc[mi][2], a[mi], bf[1][0], bf[1][2]);
                mma_fp16(acc[mi][3], a[mi], bf[1][1], bf[1][3]);
            }
        }
    }

    // write this split's partial
    float* base = g_part + (size_t)split * MDIM * NDIM;
#pragma unroll
    for (int mi = 0; mi < 4; mi++) {
        int r0 = m0 + wm + mi * 16 + lr;
#pragma unroll
        for (int ni = 0; ni < 4; ni++) {
            int c0 = wc + ni * 8 + 2 * lk;
            *reinterpret_cast<float2*>(base + (size_t)r0 * NDIM + c0) =
                make_float2(acc[mi][ni][0], acc[mi][ni][1]);
            *reinterpret_cast<float2*>(base + (size_t)(r0 + 8) * NDIM + c0) =
                make_float2(acc[mi][ni][2], acc[mi][ni][3]);
        }
    }

    // fused reduction: last CTA for this tile sums all splits in fixed order (deterministic)
    __threadfence();
    __shared__ int s_last;
    __syncthreads();
    if (tid == 0) s_last = (atomicAdd(&g_cnt[tile], 1) == SPLITS - 1) ? 1 : 0;
    __syncthreads();
    if (s_last) {
        const size_t t4 = (size_t)m0 * NDIM / 4;
#pragma unroll
        for (int j = 0; j < 16; j++) {
            size_t idx = t4 + (size_t)tid + (size_t)j * 256;
            float4 a4 = __ldcg(reinterpret_cast<const float4*>(g_part) + idx);
#pragma unroll
            for (int s = 1; s < SPLITS; s++) {
                float4 v = __ldcg(reinterpret_cast<const float4*>(g_part) +
                                  (size_t)s * (MDIM * NDIM / 4) + idx);
                a4.x += v.x; a4.y += v.y; a4.z += v.z; a4.w += v.w;
            }
            reinterpret_cast<float4*>(out)[idx] = a4;
        }
    }
}

// ---------------- launch ----------------
extern "C" void kernel_launch(void* const* d_in, const int* in_sizes, int n_in,
                              void* d_out, int out_size) {
    const float* input = (const float*)d_in[0];
    const float* w2v   = (const float*)d_in[1];
    if (n_in >= 2 && in_sizes[0] == 50000 * 128) {  // defensive: identify by size
        input = (const float*)d_in[1];
        w2v   = (const float*)d_in[0];
    }
    cudaFuncSetAttribute(gemm_fp16, cudaFuncAttributeMaxDynamicSharedMemorySize, SMEM_TOTAL);

    prep_b<<<dim3(KPAD / 32, NDIM / 32), dim3(32, 8)>>>(w2v);
    gemm_fp16<<<dim3(MDIM / BM, SPLITS), 256, SMEM_TOTAL>>>((float*)d_out, input);
}